// round 7
// baseline (speedup 1.0000x reference)
#include <cuda_runtime.h>
#include <cuda_fp16.h>

// NaturalCubicSplinePotential — GB300 sm_103a
//
// R6: split-precision table to cut L1TEX gather bytes (measured: LDS.128 costs
// ~8 wavefronts even conflict-free, so gather BYTES are the wall).
//   T1: float2 (a,b)  8B entries, 16-slot interleave (128B stride) -> LDS.64,
//       conflict-free for any phase granularity.
//   T2: half2  (c,d)  4B entries, 16-slot interleave (64B stride)  -> LDS.32.
// Precision: |v|<=0.5 so c,d terms are damped x0.25/x0.125; fp16 (c,d) adds
// ~3e-5 per-elem bias -> predicted sum rel_err ~5e-5 (tolerance 1e-3).
// Smem ~49KB -> 4 CTAs/SM -> 64 regs available: __launch_bounds__(256,4),
// unroll 8 for deeper LDG batching (R5 was pinched at 40 regs).
//
// Retained: closed-form [1,4,1] inverse (31-tap conv), padded 256 intervals
// (no clamp), magic-number floor + midpoint recentering, fused deterministic
// last-block reduction.

#define NM 8
#define NN 128
#define TABN 256
#define PADL 64
#define NSLOT 16
#define EVAL_BLOCKS 1024
#define F4_PER_BLOCK 4096
#define NTHREADS 256
#define CONV_R 15

__device__ float g_part[EVAL_BLOCKS];
__device__ unsigned int g_ticket;   // zero-init; self-resets each call

#define LOG2_LAM 1.89996863f        // log2(2+sqrt(3))
#define INV_D0   1.07735027f        // 1/(1-lam^-2)
#define MAGIC    12582912.0f        // 1.5 * 2^23
#define MAGIC_I  0x4B400000

// ---------------------------------------------------------------------------
__device__ __forceinline__ void eval_lane(float xv,
                                          const float2* __restrict__ t1,
                                          const __half2* __restrict__ t2,
                                          float& acc)
{
    // t5 = (x+4)*127/8 + 64 - 0.5   (pads folded: 4*15.875 + 63.5 = 127.0)
    const float t5 = __fmaf_rn(xv, 15.875f, 127.0f);
    const float tm = t5 + MAGIC;                    // round(t5) == floor(t) a.e.
    const int   i  = __float_as_int(tm) - MAGIC_I;
    const float v  = t5 - (tm - MAGIC);             // v = u - 0.5 in [-0.5,0.5)
    const float2  ab = t1[i * NSLOT];               // LDS.64, conflict-free
    const __half2 cd = t2[i * NSLOT];               // LDS.32
    const float2  f  = __half22float2(cd);
    acc += __fmaf_rn(v, __fmaf_rn(v, __fmaf_rn(v, f.y, f.x), ab.y), ab.x);
}

__global__ void __launch_bounds__(NTHREADS, 4)
eval_kernel(const float4* __restrict__ x4,
            const float* __restrict__ nodal,
            float* __restrict__ out)
{
    __shared__ float2  tab1[TABN * NSLOT];              // 32 KB (a,b)
    __shared__ __half2 tab2[TABN * NSLOT];              // 16 KB (c,d)
    __shared__ float  ysh[NN];
    __shared__ float  pw[256];                          // pw[k] = lam^{-k}
    __shared__ float  srsh[NN + 2 * (CONV_R + 1)];      // padded (-1)^j * r_j
    __shared__ float  csh[NN];
    __shared__ float  wsum[NTHREADS / 32];
    __shared__ bool   amLast;

    const int tid = threadIdx.x;
    // slab (bs,f) = 65536 elems = 4 blocks; marginal index = slab & 7
    const int m = (blockIdx.x >> 2) & 7;

    // ---- prologue: closed-form spline solve --------------------------------
    if (tid < NN)
        ysh[tid] = nodal[m * NN + tid];
    pw[tid] = exp2f(-LOG2_LAM * (float)tid);
    if (tid < NN + 2 * (CONV_R + 1))
        srsh[tid] = 0.0f;
    __syncthreads();

    const float inv_h2 = (127.0f / 8.0f) * (127.0f / 8.0f);
    if (tid >= 1 && tid <= 126) {
        float r = 3.0f * (ysh[tid - 1] - 2.0f * ysh[tid] + ysh[tid + 1]) * inv_h2;
        srsh[(CONV_R + 1) + tid] = (tid & 1) ? -r : r;
    }
    __syncthreads();

    if (tid < NN) {
        const int i = tid;
        float c = 0.0f;
        if (i >= 1 && i <= 126) {
#pragma unroll
            for (int dj = -CONV_R; dj <= CONV_R; ++dj) {
                const int j  = i + dj;
                const int jc = min(max(j, 1), 126);
                const int mi = min(i, jc);
                const int mx = max(i, jc);
                const float w = pw[(dj < 0 ? -dj : dj) + 1]
                              * (1.0f - pw[2 * mi])
                              * (1.0f - pw[2 * (127 - mx)]);
                c = __fmaf_rn(w, srsh[(CONV_R + 1) + j], c);
            }
            c *= INV_D0;
            if (i & 1) c = -c;
        }
        csh[i] = c;
    }
    __syncthreads();

    // ---- padded + midpoint-recentered split table --------------------------
    {
        const float h  = 8.0f / 127.0f;
        const float h2 = h * h;
        const int j  = tid;
        const int it = j - PADL;
        const int k  = min(max(it, 0), 126);
        const float s = (float)(it - k) + 0.5f;     // shift incl. midpoint

        const float A  = ysh[k];
        const float c0 = csh[k];
        const float c1 = csh[k + 1];
        const float B  = (ysh[k + 1] - A) - h2 * (2.0f * c0 + c1) * (1.0f / 3.0f);
        const float C  = c0 * h2;
        const float D  = (c1 - c0) * h2 * (1.0f / 3.0f);

        const float2  ab = make_float2(A + s * (B + s * (C + s * D)),
                                       B + s * (2.0f * C + 3.0f * D * s));
        const __half2 cd = __floats2half2_rn(C + 3.0f * D * s, D);
#pragma unroll
        for (int sl = 0; sl < NSLOT; ++sl) {
            tab1[j * NSLOT + sl] = ab;
            tab2[j * NSLOT + sl] = cd;
        }
    }
    __syncthreads();

    // ---- main evaluation loop ----------------------------------------------
    const float2*  t1 = tab1 + (tid & (NSLOT - 1));
    const __half2* t2 = tab2 + (tid & (NSLOT - 1));
    const float4* p = x4 + (size_t)blockIdx.x * F4_PER_BLOCK + tid;

    float a0 = 0.0f, a1 = 0.0f, a2 = 0.0f, a3 = 0.0f;
#pragma unroll 8
    for (int it = 0; it < F4_PER_BLOCK / NTHREADS; ++it) {
        const float4 v = p[it * NTHREADS];
        eval_lane(v.x, t1, t2, a0);
        eval_lane(v.y, t1, t2, a1);
        eval_lane(v.z, t1, t2, a2);
        eval_lane(v.w, t1, t2, a3);
    }

    float s = (a0 + a1) + (a2 + a3);
#pragma unroll
    for (int o = 16; o > 0; o >>= 1)
        s += __shfl_xor_sync(0xFFFFFFFFu, s, o);

    if ((tid & 31) == 0)
        wsum[tid >> 5] = s;
    __syncthreads();

    if (tid == 0) {
        float t = 0.0f;
#pragma unroll
        for (int w = 0; w < NTHREADS / 32; ++w)
            t += wsum[w];
        g_part[blockIdx.x] = t;
        __threadfence();
        const unsigned int ticket = atomicAdd(&g_ticket, 1u);
        amLast = (ticket == EVAL_BLOCKS - 1);
    }
    __syncthreads();

    // ---- last block: deterministic fixed-order final reduction -------------
    if (amLast) {
        __threadfence();
        float r = 0.0f;
#pragma unroll
        for (int i = 0; i < EVAL_BLOCKS / NTHREADS; ++i)
            r += g_part[tid + i * NTHREADS];

        __shared__ float sh[NTHREADS];
        sh[tid] = r;
        __syncthreads();
#pragma unroll
        for (int st = NTHREADS / 2; st > 0; st >>= 1) {
            if (tid < st)
                sh[tid] += sh[tid + st];
            __syncthreads();
        }
        if (tid == 0) {
            out[0] = sh[0];
            g_ticket = 0u;   // reset for next call / graph replay
        }
    }
}

// ---------------------------------------------------------------------------
extern "C" void kernel_launch(void* const* d_in, const int* in_sizes, int n_in,
                              void* d_out, int out_size)
{
    const float* x     = (const float*)d_in[0];        // (32,8,256,256) fp32
    const float* nodal = (const float*)d_in[1];        // (8,128) fp32
    float* out = (float*)d_out;

    eval_kernel<<<EVAL_BLOCKS, NTHREADS>>>((const float4*)x, nodal, out);
}

// round 8
// speedup vs baseline: 1.5223x; 1.5223x over previous
#include <cuda_runtime.h>

// NaturalCubicSplinePotential — GB300 sm_103a
//
// R7: revert to R5's verified conflict-free float4/NSLOT=8 gather; attack the
// latency/occupancy gap instead:
//  - TABN 256 -> 224 (PADL=48, covers |x|<=7): table 28KB, total ~31KB smem
//    -> 7 CTAs/SM -> strict single wave (1024 = 136*7 + 12*6), no 2nd-wave tail
//  - __launch_bounds__(256, 7): regs<=36 so 7 CTAs fit the 64K register file
// Measured-validated model: L1 floor 36 cyc/warp-iter (4x LDS.128@4wf*2cyc +
// LDG@4wf); R5's 11us wall-vs-busy gap was occupancy/tail, targeted here.
//
// Retained: closed-form [1,4,1] tridiagonal inverse (31-tap conv), padded
// intervals (no clamp in hot loop), magic-number floor + midpoint recentering,
// fused deterministic last-block reduction.

#define NM 8
#define NN 128
#define TABN 224
#define PADL 48
#define NSLOT 8
#define EVAL_BLOCKS 1024
#define F4_PER_BLOCK 4096
#define NTHREADS 256
#define CONV_R 15

__device__ float g_part[EVAL_BLOCKS];
__device__ unsigned int g_ticket;   // zero-init; self-resets each call

#define LOG2_LAM 1.89996863f        // log2(2+sqrt(3))
#define INV_D0   1.07735027f        // 1/(1-lam^-2)
#define MAGIC    12582912.0f        // 1.5 * 2^23
#define MAGIC_I  0x4B400000

// ---------------------------------------------------------------------------
__device__ __forceinline__ void eval_lane(float xv, const float4* __restrict__ tslot,
                                          float& acc)
{
    // t = (x+4)*15.875 + 48 (pad offset), midpoint-shifted: t5 = t - 0.5
    //   = x*15.875 + 111.0
    const float t5 = __fmaf_rn(xv, 15.875f, 111.0f);
    const float tm = t5 + MAGIC;                    // round(t5) == floor(t) a.e.
    const int   i  = __float_as_int(tm) - MAGIC_I;
    const float v  = t5 - (tm - MAGIC);             // v = u - 0.5 in [-0.5,0.5)
    const float4 cf = tslot[i * NSLOT];             // conflict-free slot gather
    acc += __fmaf_rn(v, __fmaf_rn(v, __fmaf_rn(v, cf.w, cf.z), cf.y), cf.x);
}

__global__ void __launch_bounds__(NTHREADS, 7)
eval_kernel(const float4* __restrict__ x4,
            const float* __restrict__ nodal,
            float* __restrict__ out)
{
    __shared__ float4 tab[TABN * NSLOT];                // 28 KB, lane-slotted
    __shared__ float  ysh[NN];
    __shared__ float  pw[256];                          // pw[k] = lam^{-k}
    __shared__ float  srsh[NN + 2 * (CONV_R + 1)];      // padded (-1)^j * r_j
    __shared__ float  csh[NN];
    __shared__ float  wsum[NTHREADS / 32];
    __shared__ bool   amLast;

    const int tid = threadIdx.x;
    // slab (bs,f) = 65536 elems = 4 blocks; marginal index = slab & 7
    const int m = (blockIdx.x >> 2) & 7;

    // ---- prologue: closed-form spline solve --------------------------------
    if (tid < NN)
        ysh[tid] = nodal[m * NN + tid];
    pw[tid] = exp2f(-LOG2_LAM * (float)tid);
    if (tid < NN + 2 * (CONV_R + 1))
        srsh[tid] = 0.0f;
    __syncthreads();

    const float inv_h2 = (127.0f / 8.0f) * (127.0f / 8.0f);
    if (tid >= 1 && tid <= 126) {
        float r = 3.0f * (ysh[tid - 1] - 2.0f * ysh[tid] + ysh[tid + 1]) * inv_h2;
        srsh[(CONV_R + 1) + tid] = (tid & 1) ? -r : r;
    }
    __syncthreads();

    if (tid < NN) {
        const int i = tid;
        float c = 0.0f;
        if (i >= 1 && i <= 126) {
#pragma unroll
            for (int dj = -CONV_R; dj <= CONV_R; ++dj) {
                const int j  = i + dj;
                const int jc = min(max(j, 1), 126);
                const int mi = min(i, jc);
                const int mx = max(i, jc);
                const float w = pw[(dj < 0 ? -dj : dj) + 1]
                              * (1.0f - pw[2 * mi])
                              * (1.0f - pw[2 * (127 - mx)]);
                c = __fmaf_rn(w, srsh[(CONV_R + 1) + j], c);
            }
            c *= INV_D0;
            if (i & 1) c = -c;
        }
        csh[i] = c;
    }
    __syncthreads();

    // ---- padded + midpoint-recentered table, 8 slots -----------------------
    if (tid < TABN) {
        const float h  = 8.0f / 127.0f;
        const float h2 = h * h;
        const int j  = tid;
        const int it = j - PADL;
        const int k  = min(max(it, 0), 126);
        const float s = (float)(it - k) + 0.5f;     // shift incl. midpoint

        const float A  = ysh[k];
        const float c0 = csh[k];
        const float c1 = csh[k + 1];
        const float B  = (ysh[k + 1] - A) - h2 * (2.0f * c0 + c1) * (1.0f / 3.0f);
        const float C  = c0 * h2;
        const float D  = (c1 - c0) * h2 * (1.0f / 3.0f);

        const float4 cf = make_float4(A + s * (B + s * (C + s * D)),
                                      B + s * (2.0f * C + 3.0f * D * s),
                                      C + 3.0f * D * s,
                                      D);
#pragma unroll
        for (int sl = 0; sl < NSLOT; ++sl)
            tab[j * NSLOT + sl] = cf;
    }
    __syncthreads();

    // ---- main evaluation loop ----------------------------------------------
    const float4* tslot = tab + (tid & 7);          // this lane's bank-quad
    const float4* p = x4 + (size_t)blockIdx.x * F4_PER_BLOCK + tid;

    float a0 = 0.0f, a1 = 0.0f, a2 = 0.0f, a3 = 0.0f;
#pragma unroll 4
    for (int it = 0; it < F4_PER_BLOCK / NTHREADS; ++it) {
        const float4 v = p[it * NTHREADS];
        eval_lane(v.x, tslot, a0);
        eval_lane(v.y, tslot, a1);
        eval_lane(v.z, tslot, a2);
        eval_lane(v.w, tslot, a3);
    }

    float s = (a0 + a1) + (a2 + a3);
#pragma unroll
    for (int o = 16; o > 0; o >>= 1)
        s += __shfl_xor_sync(0xFFFFFFFFu, s, o);

    if ((tid & 31) == 0)
        wsum[tid >> 5] = s;
    __syncthreads();

    if (tid == 0) {
        float t = 0.0f;
#pragma unroll
        for (int w = 0; w < NTHREADS / 32; ++w)
            t += wsum[w];
        g_part[blockIdx.x] = t;
        __threadfence();
        const unsigned int ticket = atomicAdd(&g_ticket, 1u);
        amLast = (ticket == EVAL_BLOCKS - 1);
    }
    __syncthreads();

    // ---- last block: deterministic fixed-order final reduction -------------
    if (amLast) {
        __threadfence();
        float r = 0.0f;
#pragma unroll
        for (int i = 0; i < EVAL_BLOCKS / NTHREADS; ++i)
            r += g_part[tid + i * NTHREADS];

        __shared__ float sh[NTHREADS];
        sh[tid] = r;
        __syncthreads();
#pragma unroll
        for (int st = NTHREADS / 2; st > 0; st >>= 1) {
            if (tid < st)
                sh[tid] += sh[tid + st];
            __syncthreads();
        }
        if (tid == 0) {
            out[0] = sh[0];
            g_ticket = 0u;   // reset for next call / graph replay
        }
    }
}

// ---------------------------------------------------------------------------
extern "C" void kernel_launch(void* const* d_in, const int* in_sizes, int n_in,
                              void* d_out, int out_size)
{
    const float* x     = (const float*)d_in[0];        // (32,8,256,256) fp32
    const float* nodal = (const float*)d_in[1];        // (8,128) fp32
    float* out = (float*)d_out;

    eval_kernel<<<EVAL_BLOCKS, NTHREADS>>>((const float4*)x, nodal, out);
}